// round 11
// baseline (speedup 1.0000x reference)
#include <cuda_runtime.h>
#include <cuda_bf16.h>
#include <math.h>
#include <stdint.h>

#define N_NODES 40000
#define M_PAD   40064          // 313 * 128
#define N_EDGES 640000
#define DIM 256
#define NHEAD 8
#define DHEAD 32
#define DFF 1024
#define QK_SCALE 0.0625f       // 256^-0.5

// ---------------- scratch (device globals; zero-initialized; no allocations) ----
__device__ __align__(16) float g_qkv[(size_t)M_PAD * 768];     // q|k|v per node
__device__ __align__(16) float g_scores[(size_t)NHEAD * N_EDGES]; // head-major, CSR order
__device__ __align__(16) float g_x[(size_t)N_NODES * DIM];     // x = triplet + agg

__device__ int g_deg[N_NODES];
__device__ int g_off[N_NODES + 1];
__device__ int g_pos[N_NODES];
__device__ int g_eidx[N_EDGES];
__device__ int g_perm[N_EDGES];

__device__ __align__(16) __nv_bfloat16 g_hln_h[(size_t)M_PAD * DIM];
__device__ __align__(16) __nv_bfloat16 g_hln_l[(size_t)M_PAD * DIM];
__device__ __align__(16) __nv_bfloat16 g_yln_h[(size_t)M_PAD * DIM];
__device__ __align__(16) __nv_bfloat16 g_yln_l[(size_t)M_PAD * DIM];
__device__ __align__(16) __nv_bfloat16 g_hid_h[(size_t)M_PAD * DFF];
__device__ __align__(16) __nv_bfloat16 g_hid_l[(size_t)M_PAD * DFF];

__device__ __align__(16) __nv_bfloat16 g_wq_h[768 * 256];   // [n][k]
__device__ __align__(16) __nv_bfloat16 g_wq_l[768 * 256];
__device__ __align__(16) __nv_bfloat16 g_wi_h[1024 * 256];
__device__ __align__(16) __nv_bfloat16 g_wi_l[1024 * 256];
__device__ __align__(16) __nv_bfloat16 g_wo_h[256 * 1024];
__device__ __align__(16) __nv_bfloat16 g_wo_l[256 * 1024];

// ---------------- PTX helpers (portable ISA only: sm_80-era) ----------------
__device__ __forceinline__ uint32_t smem_u32(const void* p) {
    return (uint32_t)__cvta_generic_to_shared(p);
}

__device__ __forceinline__ void cp16(uint32_t dst, const void* src) {
    asm volatile("cp.async.cg.shared.global [%0], [%1], 16;" :: "r"(dst), "l"(src));
}

__device__ __forceinline__ void ldsm_x4(uint32_t* r, uint32_t addr) {
    asm volatile("ldmatrix.sync.aligned.m8n8.x4.shared.b16 {%0,%1,%2,%3}, [%4];"
                 : "=r"(r[0]), "=r"(r[1]), "=r"(r[2]), "=r"(r[3]) : "r"(addr));
}

__device__ __forceinline__ void mma16816(float* c, const uint32_t* a, const uint32_t* b) {
    asm volatile(
        "mma.sync.aligned.m16n8k16.row.col.f32.bf16.bf16.f32 "
        "{%0,%1,%2,%3}, {%4,%5,%6,%7}, {%8,%9}, {%0,%1,%2,%3};"
        : "+f"(c[0]), "+f"(c[1]), "+f"(c[2]), "+f"(c[3])
        : "r"(a[0]), "r"(a[1]), "r"(a[2]), "r"(a[3]), "r"(b[0]), "r"(b[1]));
}

// ---------------- weight prep: transpose + bf16 hi/lo split -----------------
__global__ void wprep_kernel(const float* __restrict__ W, __nv_bfloat16* __restrict__ Bh,
                             __nv_bfloat16* __restrict__ Bl, int K, int Nt) {
    int idx = blockIdx.x * blockDim.x + threadIdx.x;
    if (idx >= K * Nt) return;
    int k = idx / Nt, n = idx - k * Nt;
    float v = W[idx];
    __nv_bfloat16 h = __float2bfloat16(v);
    float lo = v - __bfloat162float(h);
    Bh[(size_t)n * K + k] = h;
    Bl[(size_t)n * K + k] = __float2bfloat16(lo);
}

// ---------------- layernorm with bf16 hi/lo split output --------------------
__device__ __forceinline__ void split_store4(__nv_bfloat16* __restrict__ oh,
                                             __nv_bfloat16* __restrict__ ol,
                                             size_t idx, float4 v) {
    __nv_bfloat16 h0 = __float2bfloat16(v.x), h1 = __float2bfloat16(v.y);
    __nv_bfloat16 h2 = __float2bfloat16(v.z), h3 = __float2bfloat16(v.w);
    __nv_bfloat162 a, b, c, d;
    a.x = h0; a.y = h1; b.x = h2; b.y = h3;
    c.x = __float2bfloat16(v.x - __bfloat162float(h0));
    c.y = __float2bfloat16(v.y - __bfloat162float(h1));
    d.x = __float2bfloat16(v.z - __bfloat162float(h2));
    d.y = __float2bfloat16(v.w - __bfloat162float(h3));
    *(__nv_bfloat162*)(oh + idx)     = a;
    *(__nv_bfloat162*)(oh + idx + 2) = b;
    *(__nv_bfloat162*)(ol + idx)     = c;
    *(__nv_bfloat162*)(ol + idx + 2) = d;
}

__global__ void ln_split_kernel(const float* __restrict__ x, const float* __restrict__ g,
                                const float* __restrict__ b,
                                __nv_bfloat16* __restrict__ oh, __nv_bfloat16* __restrict__ ol) {
    int row = blockIdx.x * 8 + threadIdx.y;
    if (row >= N_NODES) return;
    int lane = threadIdx.x;
    const float4* xr = (const float4*)(x + (size_t)row * DIM);
    float4 v0 = xr[lane];
    float4 v1 = xr[lane + 32];
    float sum = v0.x + v0.y + v0.z + v0.w + v1.x + v1.y + v1.z + v1.w;
    float sq  = v0.x*v0.x + v0.y*v0.y + v0.z*v0.z + v0.w*v0.w
              + v1.x*v1.x + v1.y*v1.y + v1.z*v1.z + v1.w*v1.w;
    #pragma unroll
    for (int o = 16; o > 0; o >>= 1) {
        sum += __shfl_xor_sync(0xFFFFFFFFu, sum, o);
        sq  += __shfl_xor_sync(0xFFFFFFFFu, sq,  o);
    }
    float mu = sum * (1.f / DIM);
    float var = sq * (1.f / DIM) - mu * mu;
    float rstd = rsqrtf(var + 1e-5f);
    const float4* gg = (const float4*)g;
    const float4* bb = (const float4*)b;
    float4 g0 = gg[lane], g1 = gg[lane + 32];
    float4 b0 = bb[lane], b1 = bb[lane + 32];
    float4 o0, o1;
    o0.x = (v0.x - mu) * rstd * g0.x + b0.x;
    o0.y = (v0.y - mu) * rstd * g0.y + b0.y;
    o0.z = (v0.z - mu) * rstd * g0.z + b0.z;
    o0.w = (v0.w - mu) * rstd * g0.w + b0.w;
    o1.x = (v1.x - mu) * rstd * g1.x + b1.x;
    o1.y = (v1.y - mu) * rstd * g1.y + b1.y;
    o1.z = (v1.z - mu) * rstd * g1.z + b1.z;
    o1.w = (v1.w - mu) * rstd * g1.w + b1.w;
    size_t base = (size_t)row * DIM;
    split_store4(oh, ol, base + lane * 4, o0);
    split_store4(oh, ol, base + 128 + lane * 4, o1);
}

// ---------------- CSR build ----------------
__global__ void csr_zero_kernel() {
    int i = blockIdx.x * blockDim.x + threadIdx.x;
    if (i < N_NODES) g_deg[i] = 0;
}

__global__ void csr_count_kernel(const int* __restrict__ dst) {
    int e = blockIdx.x * blockDim.x + threadIdx.x;
    if (e < N_EDGES) atomicAdd(&g_deg[dst[e]], 1);
}

__global__ void csr_scan_kernel() {
    __shared__ int part[1024];
    int t = threadIdx.x;
    const int CH = 40;                 // 1024 * 40 >= N_NODES
    int b = t * CH;
    int sum = 0;
    for (int i = 0; i < CH; i++) {
        int idx = b + i;
        if (idx < N_NODES) sum += g_deg[idx];
    }
    part[t] = sum;
    __syncthreads();
    for (int o = 1; o < 1024; o <<= 1) {
        int v = (t >= o) ? part[t - o] : 0;
        __syncthreads();
        part[t] += v;
        __syncthreads();
    }
    int run = (t > 0) ? part[t - 1] : 0;
    for (int i = 0; i < CH; i++) {
        int idx = b + i;
        if (idx < N_NODES) {
            g_off[idx] = run;
            g_pos[idx] = run;
            run += g_deg[idx];
        }
    }
    if (t == 0) g_off[N_NODES] = N_EDGES;
}

__global__ void csr_fill_kernel(const int* __restrict__ dst) {
    int e = blockIdx.x * blockDim.x + threadIdx.x;
    if (e >= N_EDGES) return;
    int p = atomicAdd(&g_pos[dst[e]], 1);
    g_eidx[p] = e;
    g_perm[e] = p;
}

// ---------------- mma.sync GEMM: C = A[M,K] @ B[N,K]^T (bf16x3, fp32 acc) ----
// BM=128, BN=128, BK=32, 256 threads, warp tile 32x64 (2x8 m16n8k16 frags).
// Round-8 per-ks schedule, B frags in half-batches of 4 ni to fit 128 regs
// -> 2 CTAs/SM (launch_bounds minBlocks=2).
#define STAGE_BYTES 40960
#define GEMM_SMEM   (2 * STAGE_BYTES)

__device__ __forceinline__ void gemm_prefetch(
    uint32_t sbase, int s, int tid, int m0, int n0, int kb, int K,
    const __nv_bfloat16* Ah, const __nv_bfloat16* Al,
    const __nv_bfloat16* Bh, const __nv_bfloat16* Bl) {
    uint32_t sp = sbase + s * STAGE_BYTES;
    int row  = tid >> 1;
    int half = tid & 1;
    uint32_t cb = (uint32_t)half * 32;
    size_t goff = (size_t)kb + (size_t)half * 16;
    uint32_t da = sp + row * 80 + cb;
    const __nv_bfloat16* pa  = Ah + (size_t)(m0 + row) * K + goff;
    const __nv_bfloat16* pal = Al + (size_t)(m0 + row) * K + goff;
    cp16(da, pa);              cp16(da + 16, pa + 8);
    cp16(da + 10240, pal);     cp16(da + 10240 + 16, pal + 8);
    uint32_t db = sp + 20480 + row * 80 + cb;
    const __nv_bfloat16* pb  = Bh + (size_t)(n0 + row) * K + goff;
    const __nv_bfloat16* pbl = Bl + (size_t)(n0 + row) * K + goff;
    cp16(db, pb);              cp16(db + 16, pb + 8);
    cp16(db + 10240, pbl);     cp16(db + 10240 + 16, pbl + 8);
    asm volatile("cp.async.commit_group;" ::: "memory");
}

__global__ __launch_bounds__(256, 2) void gemm_mma_kernel(
    const __nv_bfloat16* __restrict__ Ah, const __nv_bfloat16* __restrict__ Al,
    const __nv_bfloat16* __restrict__ Bh, const __nv_bfloat16* __restrict__ Bl,
    const float* __restrict__ bias, const float* __restrict__ addend,
    float* __restrict__ outf,
    __nv_bfloat16* __restrict__ oh, __nv_bfloat16* __restrict__ ol,
    int K, int Ntot, int mode) {
    extern __shared__ char smem[];
    const uint32_t sbase = smem_u32(smem);
    const int tid = threadIdx.x;
    const int wid = tid >> 5, lane = tid & 31;
    const int wm = wid & 3, wn = wid >> 2;      // wm 0..3, wn 0..1
    const int m0 = blockIdx.y * 128;
    const int n0 = blockIdx.x * 128;

    float acc[2][8][4];
    #pragma unroll
    for (int i = 0; i < 2; i++)
        #pragma unroll
        for (int j = 0; j < 8; j++)
            #pragma unroll
            for (int q = 0; q < 4; q++) acc[i][j][q] = 0.f;

    const int nk = K >> 5;
    gemm_prefetch(sbase, 0, tid, m0, n0, 0, K, Ah, Al, Bh, Bl);

    const int r16 = lane & 15, ah8 = (lane >> 4) * 8;
    const int b8  = lane & 7;
    const int bmi = lane >> 3;
    const int bni = (bmi >> 1) * 8;
    const int bk8 = (bmi & 1) * 8;

    for (int kt = 0; kt < nk; kt++) {
        asm volatile("cp.async.wait_group 0;" ::: "memory");
        __syncthreads();
        if (kt + 1 < nk)
            gemm_prefetch(sbase, (kt + 1) & 1, tid, m0, n0, (kt + 1) << 5, K, Ah, Al, Bh, Bl);
        uint32_t sp = sbase + (kt & 1) * STAGE_BYTES;
        #pragma unroll
        for (int ks = 0; ks < 2; ks++) {
            uint32_t ahf[2][4], alf[2][4];
            #pragma unroll
            for (int mi = 0; mi < 2; mi++) {
                uint32_t a = sp + (uint32_t)(wm * 32 + mi * 16 + r16) * 80
                           + (uint32_t)(ks * 16 + ah8) * 2;
                ldsm_x4(ahf[mi], a);
                ldsm_x4(alf[mi], a + 10240);
            }
            // B frags in half-batches of 4 ni (keeps live regs < 128)
            #pragma unroll
            for (int nh = 0; nh < 2; nh++) {
                uint32_t bhf[4][2], blf[4][2];
                #pragma unroll
                for (int pq = 0; pq < 2; pq++) {
                    int pi = nh * 2 + pq;
                    uint32_t a = sp + 20480
                               + (uint32_t)(wn * 64 + pi * 16 + bni + b8) * 80
                               + (uint32_t)(ks * 16 + bk8) * 2;
                    uint32_t r[4];
                    ldsm_x4(r, a);
                    bhf[pq*2][0] = r[0]; bhf[pq*2][1] = r[1];
                    bhf[pq*2+1][0] = r[2]; bhf[pq*2+1][1] = r[3];
                    ldsm_x4(r, a + 10240);
                    blf[pq*2][0] = r[0]; blf[pq*2][1] = r[1];
                    blf[pq*2+1][0] = r[2]; blf[pq*2+1][1] = r[3];
                }
                #pragma unroll
                for (int mi = 0; mi < 2; mi++)
                    #pragma unroll
                    for (int nj = 0; nj < 4; nj++) {
                        int ni = nh * 4 + nj;
                        mma16816(acc[mi][ni], ahf[mi], bhf[nj]);
                        mma16816(acc[mi][ni], ahf[mi], blf[nj]);
                        mma16816(acc[mi][ni], alf[mi], bhf[nj]);
                    }
            }
        }
        // no trailing __syncthreads: next iteration's wait+sync orders the
        // stage overwrite (double buffer alternates stages)
    }

    // ---- epilogue ----
    const int rb = m0 + wm * 32 + (lane >> 2);
    const int cb = n0 + wn * 64 + (lane & 3) * 2;
    #pragma unroll
    for (int mi = 0; mi < 2; mi++) {
        #pragma unroll
        for (int half = 0; half < 2; half++) {
            int row = rb + mi * 16 + half * 8;
            if (row >= N_NODES) continue;
            #pragma unroll
            for (int ni = 0; ni < 8; ni++) {
                int col = cb + ni * 8;
                float v0 = acc[mi][ni][half * 2 + 0] + bias[col];
                float v1 = acc[mi][ni][half * 2 + 1] + bias[col + 1];
                if (mode == 0) {
                    *(float2*)(outf + (size_t)row * Ntot + col) = make_float2(v0, v1);
                } else if (mode == 2) {
                    const float* ap = addend + (size_t)row * Ntot + col;
                    *(float2*)(outf + (size_t)row * Ntot + col) =
                        make_float2(v0 + ap[0], v1 + ap[1]);
                } else {
                    v0 = 0.5f * v0 * (1.f + erff(v0 * 0.70710678118654752f));
                    v1 = 0.5f * v1 * (1.f + erff(v1 * 0.70710678118654752f));
                    __nv_bfloat16 h0 = __float2bfloat16(v0), h1 = __float2bfloat16(v1);
                    __nv_bfloat162 hh, ll;
                    hh.x = h0; hh.y = h1;
                    ll.x = __float2bfloat16(v0 - __bfloat162float(h0));
                    ll.y = __float2bfloat16(v1 - __bfloat162float(h1));
                    size_t base = (size_t)row * Ntot + col;
                    *(__nv_bfloat162*)(oh + base) = hh;
                    *(__nv_bfloat162*)(ol + base) = ll;
                }
            }
        }
    }
}

// ---------------- edge scores: warp per edge, 8 heads; CSR-permuted output --
__global__ void score_kernel(const int* __restrict__ src, const int* __restrict__ dst) {
    int e = blockIdx.x * 8 + (threadIdx.x >> 5);
    if (e >= N_EDGES) return;
    int lane = threadIdx.x & 31;
    int h = lane >> 2, sub = lane & 3;
    int s = src[e], d = dst[e];
    const float4* qp = (const float4*)(g_qkv + (size_t)s * 768 + h * DHEAD + sub * 8);
    const float4* kp = (const float4*)(g_qkv + (size_t)d * 768 + 256 + h * DHEAD + sub * 8);
    float4 q0 = qp[0], q1 = qp[1];
    float4 k0 = kp[0], k1 = kp[1];
    float p = q0.x*k0.x + q0.y*k0.y + q0.z*k0.z + q0.w*k0.w
            + q1.x*k1.x + q1.y*k1.y + q1.z*k1.z + q1.w*k1.w;
    p += __shfl_xor_sync(0xFFFFFFFFu, p, 1);
    p += __shfl_xor_sync(0xFFFFFFFFu, p, 2);
    if (sub == 0) {
        int pos = g_perm[e];
        g_scores[(size_t)h * N_EDGES + pos] = p * QK_SCALE;
    }
}

// ---------------- softmax + aggregate (gather, no atomics, MLP-4 unroll) -----
__global__ __launch_bounds__(256) void aggregate_csr_kernel(
    const int* __restrict__ src, const float* __restrict__ triplet) {
    __shared__ int s_src[128];
    int node = blockIdx.x;
    int lane = threadIdx.x & 31;
    int h = threadIdx.x >> 5;
    int beg = g_off[node];
    int deg = g_off[node + 1] - beg;

    const float* sc_base = g_scores + (size_t)h * N_EDGES + beg;
    const float* vbase = g_qkv + 512 + h * 32 + lane;

    float m = -INFINITY;
    for (int i = lane; i < deg; i += 32) m = fmaxf(m, sc_base[i]);
    #pragma unroll
    for (int o = 16; o > 0; o >>= 1) m = fmaxf(m, __shfl_xor_sync(0xFFFFFFFFu, m, o));

    float acc = 0.f, ssum = 0.f;
    for (int base = 0; base < deg; base += 128) {
        int cnt = min(128, deg - base);
        __syncthreads();
        for (int i = threadIdx.x; i < cnt; i += 256)
            s_src[i] = src[g_eidx[beg + base + i]];
        __syncthreads();
        for (int c0 = 0; c0 < cnt; c0 += 32) {
            int i = c0 + lane;
            float w = (i < cnt) ? expf(sc_base[base + i] - m) : 0.f;
            ssum += w;
            int cc = min(32, cnt - c0);
            int jj = 0;
            for (; jj + 4 <= cc; jj += 4) {
                float w0 = __shfl_sync(0xFFFFFFFFu, w, jj);
                float w1 = __shfl_sync(0xFFFFFFFFu, w, jj + 1);
                float w2 = __shfl_sync(0xFFFFFFFFu, w, jj + 2);
                float w3 = __shfl_sync(0xFFFFFFFFu, w, jj + 3);
                int s0 = s_src[c0 + jj],     s1 = s_src[c0 + jj + 1];
                int s2 = s_src[c0 + jj + 2], s3 = s_src[c0 + jj + 3];
                float v0 = vbase[(size_t)s0 * 768];
                float v1 = vbase[(size_t)s1 * 768];
                float v2 = vbase[(size_t)s2 * 768];
                float v3 = vbase[(size_t)s3 * 768];
                acc += v0 * w0;
                acc += v1 * w1;
                acc += v2 * w2;
                acc += v3 * w3;
            }
            for (; jj < cc; jj++) {
                float wj = __shfl_sync(0xFFFFFFFFu, w, jj);
                int sj = s_src[c0 + jj];
                acc += vbase[(size_t)sj * 768] * wj;
            }
        }
    }
    #pragma unroll
    for (int o = 16; o > 0; o >>= 1) ssum += __shfl_xor_sync(0xFFFFFFFFu, ssum, o);
    float res = (ssum > 0.f) ? acc / ssum : 0.f;
    size_t idx = (size_t)node * DIM + h * 32 + lane;
    g_x[idx] = triplet[idx] + res;
}

// ---------------- launch ----------------
template <typename T>
static T* symaddr(const void* sym) {
    void* p = nullptr;
    cudaGetSymbolAddress(&p, sym);
    return (T*)p;
}

extern "C" void kernel_launch(void* const* d_in, const int* in_sizes, int n_in,
                              void* d_out, int out_size) {
    const float* triplet = (const float*)d_in[0];
    const int*   src     = (const int*)d_in[1];
    const int*   dst     = (const int*)d_in[2];
    const float* Wqkv    = (const float*)d_in[3];
    const float* bqkv    = (const float*)d_in[4];
    const float* lnag    = (const float*)d_in[5];
    const float* lnab    = (const float*)d_in[6];
    const float* lnrg    = (const float*)d_in[7];
    const float* lnrb    = (const float*)d_in[8];
    const float* W_in    = (const float*)d_in[9];
    const float* b_in    = (const float*)d_in[10];
    const float* W_out   = (const float*)d_in[11];
    const float* b_out   = (const float*)d_in[12];
    float* out = (float*)d_out;

    static bool init_done = false;
    static cudaStream_t s2;
    static cudaEvent_t ev_fork, ev_join;
    if (!init_done) {
        cudaFuncSetAttribute(gemm_mma_kernel, cudaFuncAttributeMaxDynamicSharedMemorySize,
                             GEMM_SMEM);
        cudaStreamCreateWithFlags(&s2, cudaStreamNonBlocking);
        cudaEventCreateWithFlags(&ev_fork, cudaEventDisableTiming);
        cudaEventCreateWithFlags(&ev_join, cudaEventDisableTiming);
        init_done = true;
    }

    float* qkv = symaddr<float>(g_qkv);
    float* x   = symaddr<float>(g_x);
    __nv_bfloat16* hln_h = symaddr<__nv_bfloat16>(g_hln_h);
    __nv_bfloat16* hln_l = symaddr<__nv_bfloat16>(g_hln_l);
    __nv_bfloat16* yln_h = symaddr<__nv_bfloat16>(g_yln_h);
    __nv_bfloat16* yln_l = symaddr<__nv_bfloat16>(g_yln_l);
    __nv_bfloat16* hid_h = symaddr<__nv_bfloat16>(g_hid_h);
    __nv_bfloat16* hid_l = symaddr<__nv_bfloat16>(g_hid_l);
    __nv_bfloat16* wq_h = symaddr<__nv_bfloat16>(g_wq_h);
    __nv_bfloat16* wq_l = symaddr<__nv_bfloat16>(g_wq_l);
    __nv_bfloat16* wi_h = symaddr<__nv_bfloat16>(g_wi_h);
    __nv_bfloat16* wi_l = symaddr<__nv_bfloat16>(g_wi_l);
    __nv_bfloat16* wo_h = symaddr<__nv_bfloat16>(g_wo_h);
    __nv_bfloat16* wo_l = symaddr<__nv_bfloat16>(g_wo_l);

    dim3 lnblk(32, 8);

    // fork side stream: CSR build + FFN weight prep (needed only later)
    cudaEventRecord(ev_fork, 0);
    cudaStreamWaitEvent(s2, ev_fork, 0);
    csr_zero_kernel<<<(N_NODES + 255) / 256, 256, 0, s2>>>();
    csr_count_kernel<<<(N_EDGES + 255) / 256, 256, 0, s2>>>(dst);
    csr_scan_kernel<<<1, 1024, 0, s2>>>();
    csr_fill_kernel<<<(N_EDGES + 255) / 256, 256, 0, s2>>>(dst);
    wprep_kernel<<<(256 * 1024 + 255) / 256, 256, 0, s2>>>(W_in, wi_h, wi_l, 256, 1024);
    wprep_kernel<<<(1024 * 256 + 255) / 256, 256, 0, s2>>>(W_out, wo_h, wo_l, 1024, 256);
    cudaEventRecord(ev_join, s2);

    // main stream: QKV pipeline
    wprep_kernel<<<(256 * 768 + 255) / 256, 256>>>(Wqkv, wq_h, wq_l, 256, 768);
    ln_split_kernel<<<N_NODES / 8, lnblk>>>(triplet, lnag, lnab, hln_h, hln_l);
    gemm_mma_kernel<<<dim3(768 / 128, M_PAD / 128), 256, GEMM_SMEM>>>(
        hln_h, hln_l, wq_h, wq_l, bqkv, nullptr, qkv, nullptr, nullptr, 256, 768, 0);

    // join: score/aggregate need CSR
    cudaStreamWaitEvent(0, ev_join, 0);
    score_kernel<<<N_EDGES / 8, 256>>>(src, dst);
    aggregate_csr_kernel<<<N_NODES, 256>>>(src, triplet);

    // LN2 + FFN
    ln_split_kernel<<<N_NODES / 8, lnblk>>>(x, lnrg, lnrb, yln_h, yln_l);
    gemm_mma_kernel<<<dim3(DFF / 128, M_PAD / 128), 256, GEMM_SMEM>>>(
        yln_h, yln_l, wi_h, wi_l, b_in, nullptr, nullptr, hid_h, hid_l, 256, DFF, 1);
    gemm_mma_kernel<<<dim3(DIM / 128, M_PAD / 128), 256, GEMM_SMEM>>>(
        hid_h, hid_l, wo_h, wo_l, b_out, x, out, nullptr, nullptr, DFF, DIM, 2);
}

// round 12
// speedup vs baseline: 1.4917x; 1.4917x over previous
#include <cuda_runtime.h>
#include <cuda_bf16.h>
#include <math.h>
#include <stdint.h>

#define N_NODES 40000
#define M_PAD   40064          // 313 * 128
#define N_EDGES 640000
#define DIM 256
#define NHEAD 8
#define DHEAD 32
#define DFF 1024
#define QK_SCALE 0.0625f       // 256^-0.5

// ---------------- scratch (device globals; zero-initialized; no allocations) ----
__device__ __align__(16) float g_qkv[(size_t)M_PAD * 768];     // q|k|v per node
__device__ __align__(16) float g_scores[(size_t)NHEAD * N_EDGES]; // head-major, CSR order
__device__ __align__(16) float g_x[(size_t)N_NODES * DIM];     // x = triplet + agg

__device__ int g_deg[N_NODES];
__device__ int g_off[N_NODES + 1];
__device__ int g_pos[N_NODES];
__device__ int g_eidx[N_EDGES];

__device__ __align__(16) __nv_bfloat16 g_hln_h[(size_t)M_PAD * DIM];
__device__ __align__(16) __nv_bfloat16 g_hln_l[(size_t)M_PAD * DIM];
__device__ __align__(16) __nv_bfloat16 g_yln_h[(size_t)M_PAD * DIM];
__device__ __align__(16) __nv_bfloat16 g_yln_l[(size_t)M_PAD * DIM];
__device__ __align__(16) __nv_bfloat16 g_hid_h[(size_t)M_PAD * DFF];
__device__ __align__(16) __nv_bfloat16 g_hid_l[(size_t)M_PAD * DFF];

__device__ __align__(16) __nv_bfloat16 g_wq_h[768 * 256];   // [n][k]
__device__ __align__(16) __nv_bfloat16 g_wq_l[768 * 256];
__device__ __align__(16) __nv_bfloat16 g_wi_h[1024 * 256];
__device__ __align__(16) __nv_bfloat16 g_wi_l[1024 * 256];
__device__ __align__(16) __nv_bfloat16 g_wo_h[256 * 1024];
__device__ __align__(16) __nv_bfloat16 g_wo_l[256 * 1024];

// ---------------- PTX helpers (portable ISA only: sm_80-era) ----------------
__device__ __forceinline__ uint32_t smem_u32(const void* p) {
    return (uint32_t)__cvta_generic_to_shared(p);
}

__device__ __forceinline__ void cp16(uint32_t dst, const void* src) {
    asm volatile("cp.async.cg.shared.global [%0], [%1], 16;" :: "r"(dst), "l"(src));
}

__device__ __forceinline__ void ldsm_x4(uint32_t* r, uint32_t addr) {
    asm volatile("ldmatrix.sync.aligned.m8n8.x4.shared.b16 {%0,%1,%2,%3}, [%4];"
                 : "=r"(r[0]), "=r"(r[1]), "=r"(r[2]), "=r"(r[3]) : "r"(addr));
}

__device__ __forceinline__ void mma16816(float* c, const uint32_t* a, const uint32_t* b) {
    asm volatile(
        "mma.sync.aligned.m16n8k16.row.col.f32.bf16.bf16.f32 "
        "{%0,%1,%2,%3}, {%4,%5,%6,%7}, {%8,%9}, {%0,%1,%2,%3};"
        : "+f"(c[0]), "+f"(c[1]), "+f"(c[2]), "+f"(c[3])
        : "r"(a[0]), "r"(a[1]), "r"(a[2]), "r"(a[3]), "r"(b[0]), "r"(b[1]));
}

// ---------------- weight prep: transpose + bf16 hi/lo split -----------------
__global__ void wprep_kernel(const float* __restrict__ W, __nv_bfloat16* __restrict__ Bh,
                             __nv_bfloat16* __restrict__ Bl, int K, int Nt) {
    int idx = blockIdx.x * blockDim.x + threadIdx.x;
    if (idx >= K * Nt) return;
    int k = idx / Nt, n = idx - k * Nt;
    float v = W[idx];
    __nv_bfloat16 h = __float2bfloat16(v);
    float lo = v - __bfloat162float(h);
    Bh[(size_t)n * K + k] = h;
    Bl[(size_t)n * K + k] = __float2bfloat16(lo);
}

// ---------------- layernorm with bf16 hi/lo split output --------------------
__device__ __forceinline__ void split_store4(__nv_bfloat16* __restrict__ oh,
                                             __nv_bfloat16* __restrict__ ol,
                                             size_t idx, float4 v) {
    __nv_bfloat16 h0 = __float2bfloat16(v.x), h1 = __float2bfloat16(v.y);
    __nv_bfloat16 h2 = __float2bfloat16(v.z), h3 = __float2bfloat16(v.w);
    __nv_bfloat162 a, b, c, d;
    a.x = h0; a.y = h1; b.x = h2; b.y = h3;
    c.x = __float2bfloat16(v.x - __bfloat162float(h0));
    c.y = __float2bfloat16(v.y - __bfloat162float(h1));
    d.x = __float2bfloat16(v.z - __bfloat162float(h2));
    d.y = __float2bfloat16(v.w - __bfloat162float(h3));
    *(__nv_bfloat162*)(oh + idx)     = a;
    *(__nv_bfloat162*)(oh + idx + 2) = b;
    *(__nv_bfloat162*)(ol + idx)     = c;
    *(__nv_bfloat162*)(ol + idx + 2) = d;
}

__global__ void ln_split_kernel(const float* __restrict__ x, const float* __restrict__ g,
                                const float* __restrict__ b,
                                __nv_bfloat16* __restrict__ oh, __nv_bfloat16* __restrict__ ol) {
    int row = blockIdx.x * 8 + threadIdx.y;
    if (row >= N_NODES) return;
    int lane = threadIdx.x;
    const float4* xr = (const float4*)(x + (size_t)row * DIM);
    float4 v0 = xr[lane];
    float4 v1 = xr[lane + 32];
    float sum = v0.x + v0.y + v0.z + v0.w + v1.x + v1.y + v1.z + v1.w;
    float sq  = v0.x*v0.x + v0.y*v0.y + v0.z*v0.z + v0.w*v0.w
              + v1.x*v1.x + v1.y*v1.y + v1.z*v1.z + v1.w*v1.w;
    #pragma unroll
    for (int o = 16; o > 0; o >>= 1) {
        sum += __shfl_xor_sync(0xFFFFFFFFu, sum, o);
        sq  += __shfl_xor_sync(0xFFFFFFFFu, sq,  o);
    }
    float mu = sum * (1.f / DIM);
    float var = sq * (1.f / DIM) - mu * mu;
    float rstd = rsqrtf(var + 1e-5f);
    const float4* gg = (const float4*)g;
    const float4* bb = (const float4*)b;
    float4 g0 = gg[lane], g1 = gg[lane + 32];
    float4 b0 = bb[lane], b1 = bb[lane + 32];
    float4 o0, o1;
    o0.x = (v0.x - mu) * rstd * g0.x + b0.x;
    o0.y = (v0.y - mu) * rstd * g0.y + b0.y;
    o0.z = (v0.z - mu) * rstd * g0.z + b0.z;
    o0.w = (v0.w - mu) * rstd * g0.w + b0.w;
    o1.x = (v1.x - mu) * rstd * g1.x + b1.x;
    o1.y = (v1.y - mu) * rstd * g1.y + b1.y;
    o1.z = (v1.z - mu) * rstd * g1.z + b1.z;
    o1.w = (v1.w - mu) * rstd * g1.w + b1.w;
    size_t base = (size_t)row * DIM;
    split_store4(oh, ol, base + lane * 4, o0);
    split_store4(oh, ol, base + 128 + lane * 4, o1);
}

// ---------------- CSR build ----------------
__global__ void csr_zero_kernel() {
    int i = blockIdx.x * blockDim.x + threadIdx.x;
    if (i < N_NODES) g_deg[i] = 0;
}

__global__ void csr_count_kernel(const int* __restrict__ dst) {
    int e = blockIdx.x * blockDim.x + threadIdx.x;
    if (e < N_EDGES) atomicAdd(&g_deg[dst[e]], 1);
}

__global__ void csr_scan_kernel() {
    __shared__ int part[1024];
    int t = threadIdx.x;
    const int CH = 40;                 // 1024 * 40 >= N_NODES
    int b = t * CH;
    int sum = 0;
    for (int i = 0; i < CH; i++) {
        int idx = b + i;
        if (idx < N_NODES) sum += g_deg[idx];
    }
    part[t] = sum;
    __syncthreads();
    for (int o = 1; o < 1024; o <<= 1) {
        int v = (t >= o) ? part[t - o] : 0;
        __syncthreads();
        part[t] += v;
        __syncthreads();
    }
    int run = (t > 0) ? part[t - 1] : 0;
    for (int i = 0; i < CH; i++) {
        int idx = b + i;
        if (idx < N_NODES) {
            g_off[idx] = run;
            g_pos[idx] = run;
            run += g_deg[idx];
        }
    }
    if (t == 0) g_off[N_NODES] = N_EDGES;
}

__global__ void csr_fill_kernel(const int* __restrict__ dst) {
    int e = blockIdx.x * blockDim.x + threadIdx.x;
    if (e >= N_EDGES) return;
    int p = atomicAdd(&g_pos[dst[e]], 1);
    g_eidx[p] = e;
}

// ---------------- mma.sync GEMM: C = A[M,K] @ B[N,K]^T (bf16x3, fp32 acc) ----
// BM=128, BN=128, BK=32, 256 threads, warp tile 32x64 (2x8 m16n8k16 frags).
// Round-8 schedule: per-ks fragment loads interleaved with MMAs; ~170 regs,
// 1 CTA/SM. Proven local optimum (rounds 9/11 both regressed away from it).
#define STAGE_BYTES 40960
#define GEMM_SMEM   (2 * STAGE_BYTES)

__device__ __forceinline__ void gemm_prefetch(
    uint32_t sbase, int s, int tid, int m0, int n0, int kb, int K,
    const __nv_bfloat16* Ah, const __nv_bfloat16* Al,
    const __nv_bfloat16* Bh, const __nv_bfloat16* Bl) {
    uint32_t sp = sbase + s * STAGE_BYTES;
    int row  = tid >> 1;
    int half = tid & 1;
    uint32_t cb = (uint32_t)half * 32;
    size_t goff = (size_t)kb + (size_t)half * 16;
    uint32_t da = sp + row * 80 + cb;
    const __nv_bfloat16* pa  = Ah + (size_t)(m0 + row) * K + goff;
    const __nv_bfloat16* pal = Al + (size_t)(m0 + row) * K + goff;
    cp16(da, pa);              cp16(da + 16, pa + 8);
    cp16(da + 10240, pal);     cp16(da + 10240 + 16, pal + 8);
    uint32_t db = sp + 20480 + row * 80 + cb;
    const __nv_bfloat16* pb  = Bh + (size_t)(n0 + row) * K + goff;
    const __nv_bfloat16* pbl = Bl + (size_t)(n0 + row) * K + goff;
    cp16(db, pb);              cp16(db + 16, pb + 8);
    cp16(db + 10240, pbl);     cp16(db + 10240 + 16, pbl + 8);
    asm volatile("cp.async.commit_group;" ::: "memory");
}

__global__ __launch_bounds__(256) void gemm_mma_kernel(
    const __nv_bfloat16* __restrict__ Ah, const __nv_bfloat16* __restrict__ Al,
    const __nv_bfloat16* __restrict__ Bh, const __nv_bfloat16* __restrict__ Bl,
    const float* __restrict__ bias, const float* __restrict__ addend,
    float* __restrict__ outf,
    __nv_bfloat16* __restrict__ oh, __nv_bfloat16* __restrict__ ol,
    int K, int Ntot, int mode) {
    extern __shared__ char smem[];
    const uint32_t sbase = smem_u32(smem);
    const int tid = threadIdx.x;
    const int wid = tid >> 5, lane = tid & 31;
    const int wm = wid & 3, wn = wid >> 2;      // wm 0..3, wn 0..1
    const int m0 = blockIdx.y * 128;
    const int n0 = blockIdx.x * 128;

    float acc[2][8][4];
    #pragma unroll
    for (int i = 0; i < 2; i++)
        #pragma unroll
        for (int j = 0; j < 8; j++)
            #pragma unroll
            for (int q = 0; q < 4; q++) acc[i][j][q] = 0.f;

    const int nk = K >> 5;
    gemm_prefetch(sbase, 0, tid, m0, n0, 0, K, Ah, Al, Bh, Bl);

    const int r16 = lane & 15, ah8 = (lane >> 4) * 8;
    const int b8  = lane & 7;
    const int bmi = lane >> 3;
    const int bni = (bmi >> 1) * 8;
    const int bk8 = (bmi & 1) * 8;

    for (int kt = 0; kt < nk; kt++) {
        asm volatile("cp.async.wait_group 0;" ::: "memory");
        __syncthreads();
        if (kt + 1 < nk)
            gemm_prefetch(sbase, (kt + 1) & 1, tid, m0, n0, (kt + 1) << 5, K, Ah, Al, Bh, Bl);
        uint32_t sp = sbase + (kt & 1) * STAGE_BYTES;
        #pragma unroll
        for (int ks = 0; ks < 2; ks++) {
            uint32_t ahf[2][4], alf[2][4], bhf[8][2], blf[8][2];
            #pragma unroll
            for (int mi = 0; mi < 2; mi++) {
                uint32_t a = sp + (uint32_t)(wm * 32 + mi * 16 + r16) * 80
                           + (uint32_t)(ks * 16 + ah8) * 2;
                ldsm_x4(ahf[mi], a);
                ldsm_x4(alf[mi], a + 10240);
            }
            #pragma unroll
            for (int pi = 0; pi < 4; pi++) {
                uint32_t a = sp + 20480
                           + (uint32_t)(wn * 64 + pi * 16 + bni + b8) * 80
                           + (uint32_t)(ks * 16 + bk8) * 2;
                uint32_t r[4];
                ldsm_x4(r, a);
                bhf[pi*2][0] = r[0]; bhf[pi*2][1] = r[1];
                bhf[pi*2+1][0] = r[2]; bhf[pi*2+1][1] = r[3];
                ldsm_x4(r, a + 10240);
                blf[pi*2][0] = r[0]; blf[pi*2][1] = r[1];
                blf[pi*2+1][0] = r[2]; blf[pi*2+1][1] = r[3];
            }
            #pragma unroll
            for (int mi = 0; mi < 2; mi++)
                #pragma unroll
                for (int ni = 0; ni < 8; ni++) {
                    mma16816(acc[mi][ni], ahf[mi], bhf[ni]);
                    mma16816(acc[mi][ni], ahf[mi], blf[ni]);
                    mma16816(acc[mi][ni], alf[mi], bhf[ni]);
                }
        }
        __syncthreads();
    }

    // ---- epilogue ----
    const int rb = m0 + wm * 32 + (lane >> 2);
    const int cb = n0 + wn * 64 + (lane & 3) * 2;
    #pragma unroll
    for (int mi = 0; mi < 2; mi++) {
        #pragma unroll
        for (int half = 0; half < 2; half++) {
            int row = rb + mi * 16 + half * 8;
            if (row >= N_NODES) continue;
            #pragma unroll
            for (int ni = 0; ni < 8; ni++) {
                int col = cb + ni * 8;
                float v0 = acc[mi][ni][half * 2 + 0] + bias[col];
                float v1 = acc[mi][ni][half * 2 + 1] + bias[col + 1];
                if (mode == 0) {
                    *(float2*)(outf + (size_t)row * Ntot + col) = make_float2(v0, v1);
                } else if (mode == 2) {
                    const float* ap = addend + (size_t)row * Ntot + col;
                    *(float2*)(outf + (size_t)row * Ntot + col) =
                        make_float2(v0 + ap[0], v1 + ap[1]);
                } else {
                    v0 = 0.5f * v0 * (1.f + erff(v0 * 0.70710678118654752f));
                    v1 = 0.5f * v1 * (1.f + erff(v1 * 0.70710678118654752f));
                    __nv_bfloat16 h0 = __float2bfloat16(v0), h1 = __float2bfloat16(v1);
                    __nv_bfloat162 hh, ll;
                    hh.x = h0; hh.y = h1;
                    ll.x = __float2bfloat16(v0 - __bfloat162float(h0));
                    ll.y = __float2bfloat16(v1 - __bfloat162float(h1));
                    size_t base = (size_t)row * Ntot + col;
                    *(__nv_bfloat162*)(oh + base) = hh;
                    *(__nv_bfloat162*)(ol + base) = ll;
                }
            }
        }
    }
}

// ---------------- edge scores: warp per CSR position, 8 heads ----------------
// Processing in CSR order makes consecutive warps share the same dst node
// (k-row L1 reuse) and makes score writes sector-contiguous; no perm needed.
__global__ void score_kernel(const int* __restrict__ src, const int* __restrict__ dst) {
    int pos = blockIdx.x * 8 + (threadIdx.x >> 5);
    if (pos >= N_EDGES) return;
    int e = g_eidx[pos];
    int lane = threadIdx.x & 31;
    int h = lane >> 2, sub = lane & 3;
    int s = src[e], d = dst[e];
    const float4* qp = (const float4*)(g_qkv + (size_t)s * 768 + h * DHEAD + sub * 8);
    const float4* kp = (const float4*)(g_qkv + (size_t)d * 768 + 256 + h * DHEAD + sub * 8);
    float4 q0 = qp[0], q1 = qp[1];
    float4 k0 = kp[0], k1 = kp[1];
    float p = q0.x*k0.x + q0.y*k0.y + q0.z*k0.z + q0.w*k0.w
            + q1.x*k1.x + q1.y*k1.y + q1.z*k1.z + q1.w*k1.w;
    p += __shfl_xor_sync(0xFFFFFFFFu, p, 1);
    p += __shfl_xor_sync(0xFFFFFFFFu, p, 2);
    if (sub == 0) {
        g_scores[(size_t)h * N_EDGES + pos] = p * QK_SCALE;
    }
}

// ---------------- softmax + aggregate (gather, no atomics, MLP-4 unroll) -----
__global__ __launch_bounds__(256) void aggregate_csr_kernel(
    const int* __restrict__ src, const float* __restrict__ triplet) {
    __shared__ int s_src[128];
    int node = blockIdx.x;
    int lane = threadIdx.x & 31;
    int h = threadIdx.x >> 5;
    int beg = g_off[node];
    int deg = g_off[node + 1] - beg;

    const float* sc_base = g_scores + (size_t)h * N_EDGES + beg;
    const float* vbase = g_qkv + 512 + h * 32 + lane;

    float m = -INFINITY;
    for (int i = lane; i < deg; i += 32) m = fmaxf(m, sc_base[i]);
    #pragma unroll
    for (int o = 16; o > 0; o >>= 1) m = fmaxf(m, __shfl_xor_sync(0xFFFFFFFFu, m, o));

    float acc = 0.f, ssum = 0.f;
    for (int base = 0; base < deg; base += 128) {
        int cnt = min(128, deg - base);
        __syncthreads();
        for (int i = threadIdx.x; i < cnt; i += 256)
            s_src[i] = src[g_eidx[beg + base + i]];
        __syncthreads();
        for (int c0 = 0; c0 < cnt; c0 += 32) {
            int i = c0 + lane;
            float w = (i < cnt) ? expf(sc_base[base + i] - m) : 0.f;
            ssum += w;
            int cc = min(32, cnt - c0);
            int jj = 0;
            for (; jj + 4 <= cc; jj += 4) {
                float w0 = __shfl_sync(0xFFFFFFFFu, w, jj);
                float w1 = __shfl_sync(0xFFFFFFFFu, w, jj + 1);
                float w2 = __shfl_sync(0xFFFFFFFFu, w, jj + 2);
                float w3 = __shfl_sync(0xFFFFFFFFu, w, jj + 3);
                int s0 = s_src[c0 + jj],     s1 = s_src[c0 + jj + 1];
                int s2 = s_src[c0 + jj + 2], s3 = s_src[c0 + jj + 3];
                float v0 = vbase[(size_t)s0 * 768];
                float v1 = vbase[(size_t)s1 * 768];
                float v2 = vbase[(size_t)s2 * 768];
                float v3 = vbase[(size_t)s3 * 768];
                acc += v0 * w0;
                acc += v1 * w1;
                acc += v2 * w2;
                acc += v3 * w3;
            }
            for (; jj < cc; jj++) {
                float wj = __shfl_sync(0xFFFFFFFFu, w, jj);
                int sj = s_src[c0 + jj];
                acc += vbase[(size_t)sj * 768] * wj;
            }
        }
    }
    #pragma unroll
    for (int o = 16; o > 0; o >>= 1) ssum += __shfl_xor_sync(0xFFFFFFFFu, ssum, o);
    float res = (ssum > 0.f) ? acc / ssum : 0.f;
    size_t idx = (size_t)node * DIM + h * 32 + lane;
    g_x[idx] = triplet[idx] + res;
}

// ---------------- launch ----------------
template <typename T>
static T* symaddr(const void* sym) {
    void* p = nullptr;
    cudaGetSymbolAddress(&p, sym);
    return (T*)p;
}

extern "C" void kernel_launch(void* const* d_in, const int* in_sizes, int n_in,
                              void* d_out, int out_size) {
    const float* triplet = (const float*)d_in[0];
    const int*   src     = (const int*)d_in[1];
    const int*   dst     = (const int*)d_in[2];
    const float* Wqkv    = (const float*)d_in[3];
    const float* bqkv    = (const float*)d_in[4];
    const float* lnag    = (const float*)d_in[5];
    const float* lnab    = (const float*)d_in[6];
    const float* lnrg    = (const float*)d_in[7];
    const float* lnrb    = (const float*)d_in[8];
    const float* W_in    = (const float*)d_in[9];
    const float* b_in    = (const float*)d_in[10];
    const float* W_out   = (const float*)d_in[11];
    const float* b_out   = (const float*)d_in[12];
    float* out = (float*)d_out;

    static bool init_done = false;
    static cudaStream_t s2;
    static cudaEvent_t ev_fork, ev_join;
    if (!init_done) {
        cudaFuncSetAttribute(gemm_mma_kernel, cudaFuncAttributeMaxDynamicSharedMemorySize,
                             GEMM_SMEM);
        cudaStreamCreateWithFlags(&s2, cudaStreamNonBlocking);
        cudaEventCreateWithFlags(&ev_fork, cudaEventDisableTiming);
        cudaEventCreateWithFlags(&ev_join, cudaEventDisableTiming);
        init_done = true;
    }

    float* qkv = symaddr<float>(g_qkv);
    float* x   = symaddr<float>(g_x);
    __nv_bfloat16* hln_h = symaddr<__nv_bfloat16>(g_hln_h);
    __nv_bfloat16* hln_l = symaddr<__nv_bfloat16>(g_hln_l);
    __nv_bfloat16* yln_h = symaddr<__nv_bfloat16>(g_yln_h);
    __nv_bfloat16* yln_l = symaddr<__nv_bfloat16>(g_yln_l);
    __nv_bfloat16* hid_h = symaddr<__nv_bfloat16>(g_hid_h);
    __nv_bfloat16* hid_l = symaddr<__nv_bfloat16>(g_hid_l);
    __nv_bfloat16* wq_h = symaddr<__nv_bfloat16>(g_wq_h);
    __nv_bfloat16* wq_l = symaddr<__nv_bfloat16>(g_wq_l);
    __nv_bfloat16* wi_h = symaddr<__nv_bfloat16>(g_wi_h);
    __nv_bfloat16* wi_l = symaddr<__nv_bfloat16>(g_wi_l);
    __nv_bfloat16* wo_h = symaddr<__nv_bfloat16>(g_wo_h);
    __nv_bfloat16* wo_l = symaddr<__nv_bfloat16>(g_wo_l);

    dim3 lnblk(32, 8);

    // fork side stream: CSR build + FFN weight prep (needed only later)
    cudaEventRecord(ev_fork, 0);
    cudaStreamWaitEvent(s2, ev_fork, 0);
    csr_zero_kernel<<<(N_NODES + 255) / 256, 256, 0, s2>>>();
    csr_count_kernel<<<(N_EDGES + 255) / 256, 256, 0, s2>>>(dst);
    csr_scan_kernel<<<1, 1024, 0, s2>>>();
    csr_fill_kernel<<<(N_EDGES + 255) / 256, 256, 0, s2>>>(dst);
    wprep_kernel<<<(256 * 1024 + 255) / 256, 256, 0, s2>>>(W_in, wi_h, wi_l, 256, 1024);
    wprep_kernel<<<(1024 * 256 + 255) / 256, 256, 0, s2>>>(W_out, wo_h, wo_l, 1024, 256);
    cudaEventRecord(ev_join, s2);

    // main stream: QKV pipeline
    wprep_kernel<<<(256 * 768 + 255) / 256, 256>>>(Wqkv, wq_h, wq_l, 256, 768);
    ln_split_kernel<<<N_NODES / 8, lnblk>>>(triplet, lnag, lnab, hln_h, hln_l);
    gemm_mma_kernel<<<dim3(768 / 128, M_PAD / 128), 256, GEMM_SMEM>>>(
        hln_h, hln_l, wq_h, wq_l, bqkv, nullptr, qkv, nullptr, nullptr, 256, 768, 0);

    // join: score/aggregate need CSR
    cudaStreamWaitEvent(0, ev_join, 0);
    score_kernel<<<N_EDGES / 8, 256>>>(src, dst);
    aggregate_csr_kernel<<<N_NODES, 256>>>(src, triplet);

    // LN2 + FFN
    ln_split_kernel<<<N_NODES / 8, lnblk>>>(x, lnrg, lnrb, yln_h, yln_l);
    gemm_mma_kernel<<<dim3(DFF / 128, M_PAD / 128), 256, GEMM_SMEM>>>(
        yln_h, yln_l, wi_h, wi_l, b_in, nullptr, nullptr, hid_h, hid_l, 256, DFF, 1);
    gemm_mma_kernel<<<dim3(DIM / 128, M_PAD / 128), 256, GEMM_SMEM>>>(
        hid_h, hid_l, wo_h, wo_l, b_out, x, out, nullptr, nullptr, DFF, DIM, 2);
}

// round 14
// speedup vs baseline: 1.8144x; 1.2163x over previous
#include <cuda_runtime.h>
#include <cuda_bf16.h>
#include <math.h>
#include <stdint.h>

#define N_NODES 40000
#define M_PAD   40064          // 313 * 128
#define N_EDGES 640000
#define DIM 256
#define NHEAD 8
#define DHEAD 32
#define DFF 1024
#define QK_SCALE 0.0625f       // 256^-0.5

// ---------------- scratch (device globals; zero-initialized; no allocations) ----
__device__ __align__(16) float g_qkv[(size_t)M_PAD * 768];     // q|k|v per node
__device__ __align__(16) float g_scores[(size_t)NHEAD * N_EDGES]; // head-major, CSR order
__device__ __align__(16) float g_x[(size_t)N_NODES * DIM];     // x = triplet + agg

__device__ int g_deg[N_NODES];
__device__ int g_off[N_NODES + 1];
__device__ int g_pos[N_NODES];
__device__ int g_eidx[N_EDGES];

__device__ __align__(16) __nv_bfloat16 g_hln_h[(size_t)M_PAD * DIM];
__device__ __align__(16) __nv_bfloat16 g_hln_l[(size_t)M_PAD * DIM];
__device__ __align__(16) __nv_bfloat16 g_yln_h[(size_t)M_PAD * DIM];
__device__ __align__(16) __nv_bfloat16 g_yln_l[(size_t)M_PAD * DIM];
__device__ __align__(16) __nv_bfloat16 g_hid_h[(size_t)M_PAD * DFF];
__device__ __align__(16) __nv_bfloat16 g_hid_l[(size_t)M_PAD * DFF];

__device__ __align__(16) __nv_bfloat16 g_wq_h[768 * 256];   // [n][k]
__device__ __align__(16) __nv_bfloat16 g_wi_h[1024 * 256];
__device__ __align__(16) __nv_bfloat16 g_wo_h[256 * 1024];

// ---------------- PTX helpers (portable ISA only: sm_80-era) ----------------
__device__ __forceinline__ uint32_t smem_u32(const void* p) {
    return (uint32_t)__cvta_generic_to_shared(p);
}

__device__ __forceinline__ void cp16(uint32_t dst, const void* src) {
    asm volatile("cp.async.cg.shared.global [%0], [%1], 16;" :: "r"(dst), "l"(src));
}

__device__ __forceinline__ void ldsm_x4(uint32_t* r, uint32_t addr) {
    asm volatile("ldmatrix.sync.aligned.m8n8.x4.shared.b16 {%0,%1,%2,%3}, [%4];"
                 : "=r"(r[0]), "=r"(r[1]), "=r"(r[2]), "=r"(r[3]) : "r"(addr));
}

__device__ __forceinline__ void mma16816(float* c, const uint32_t* a, const uint32_t* b) {
    asm volatile(
        "mma.sync.aligned.m16n8k16.row.col.f32.bf16.bf16.f32 "
        "{%0,%1,%2,%3}, {%4,%5,%6,%7}, {%8,%9}, {%0,%1,%2,%3};"
        : "+f"(c[0]), "+f"(c[1]), "+f"(c[2]), "+f"(c[3])
        : "r"(a[0]), "r"(a[1]), "r"(a[2]), "r"(a[3]), "r"(b[0]), "r"(b[1]));
}

// ---------------- weight prep: transpose to bf16 (hi only) ------------------
__global__ void wprep_kernel(const float* __restrict__ W, __nv_bfloat16* __restrict__ Bh,
                             int K, int Nt) {
    int idx = blockIdx.x * blockDim.x + threadIdx.x;
    if (idx >= K * Nt) return;
    int k = idx / Nt, n = idx - k * Nt;
    Bh[(size_t)n * K + k] = __float2bfloat16(W[idx]);
}

// ---------------- layernorm with bf16 hi/lo split output --------------------
__device__ __forceinline__ void split_store4(__nv_bfloat16* __restrict__ oh,
                                             __nv_bfloat16* __restrict__ ol,
                                             size_t idx, float4 v) {
    __nv_bfloat16 h0 = __float2bfloat16(v.x), h1 = __float2bfloat16(v.y);
    __nv_bfloat16 h2 = __float2bfloat16(v.z), h3 = __float2bfloat16(v.w);
    __nv_bfloat162 a, b, c, d;
    a.x = h0; a.y = h1; b.x = h2; b.y = h3;
    c.x = __float2bfloat16(v.x - __bfloat162float(h0));
    c.y = __float2bfloat16(v.y - __bfloat162float(h1));
    d.x = __float2bfloat16(v.z - __bfloat162float(h2));
    d.y = __float2bfloat16(v.w - __bfloat162float(h3));
    *(__nv_bfloat162*)(oh + idx)     = a;
    *(__nv_bfloat162*)(oh + idx + 2) = b;
    *(__nv_bfloat162*)(ol + idx)     = c;
    *(__nv_bfloat162*)(ol + idx + 2) = d;
}

__global__ void ln_split_kernel(const float* __restrict__ x, const float* __restrict__ g,
                                const float* __restrict__ b,
                                __nv_bfloat16* __restrict__ oh, __nv_bfloat16* __restrict__ ol) {
    int row = blockIdx.x * 8 + threadIdx.y;
    if (row >= N_NODES) return;
    int lane = threadIdx.x;
    const float4* xr = (const float4*)(x + (size_t)row * DIM);
    float4 v0 = xr[lane];
    float4 v1 = xr[lane + 32];
    float sum = v0.x + v0.y + v0.z + v0.w + v1.x + v1.y + v1.z + v1.w;
    float sq  = v0.x*v0.x + v0.y*v0.y + v0.z*v0.z + v0.w*v0.w
              + v1.x*v1.x + v1.y*v1.y + v1.z*v1.z + v1.w*v1.w;
    #pragma unroll
    for (int o = 16; o > 0; o >>= 1) {
        sum += __shfl_xor_sync(0xFFFFFFFFu, sum, o);
        sq  += __shfl_xor_sync(0xFFFFFFFFu, sq,  o);
    }
    float mu = sum * (1.f / DIM);
    float var = sq * (1.f / DIM) - mu * mu;
    float rstd = rsqrtf(var + 1e-5f);
    const float4* gg = (const float4*)g;
    const float4* bb = (const float4*)b;
    float4 g0 = gg[lane], g1 = gg[lane + 32];
    float4 b0 = bb[lane], b1 = bb[lane + 32];
    float4 o0, o1;
    o0.x = (v0.x - mu) * rstd * g0.x + b0.x;
    o0.y = (v0.y - mu) * rstd * g0.y + b0.y;
    o0.z = (v0.z - mu) * rstd * g0.z + b0.z;
    o0.w = (v0.w - mu) * rstd * g0.w + b0.w;
    o1.x = (v1.x - mu) * rstd * g1.x + b1.x;
    o1.y = (v1.y - mu) * rstd * g1.y + b1.y;
    o1.z = (v1.z - mu) * rstd * g1.z + b1.z;
    o1.w = (v1.w - mu) * rstd * g1.w + b1.w;
    size_t base = (size_t)row * DIM;
    split_store4(oh, ol, base + lane * 4, o0);
    split_store4(oh, ol, base + 128 + lane * 4, o1);
}

// ---------------- CSR build ----------------
__global__ void csr_zero_kernel() {
    int i = blockIdx.x * blockDim.x + threadIdx.x;
    if (i < N_NODES) g_deg[i] = 0;
}

__global__ void csr_count_kernel(const int* __restrict__ dst) {
    int e = blockIdx.x * blockDim.x + threadIdx.x;
    if (e < N_EDGES) atomicAdd(&g_deg[dst[e]], 1);
}

__global__ void csr_scan_kernel() {
    __shared__ int part[1024];
    int t = threadIdx.x;
    const int CH = 40;                 // 1024 * 40 >= N_NODES
    int b = t * CH;
    int sum = 0;
    for (int i = 0; i < CH; i++) {
        int idx = b + i;
        if (idx < N_NODES) sum += g_deg[idx];
    }
    part[t] = sum;
    __syncthreads();
    for (int o = 1; o < 1024; o <<= 1) {
        int v = (t >= o) ? part[t - o] : 0;
        __syncthreads();
        part[t] += v;
        __syncthreads();
    }
    int run = (t > 0) ? part[t - 1] : 0;
    for (int i = 0; i < CH; i++) {
        int idx = b + i;
        if (idx < N_NODES) {
            g_off[idx] = run;
            g_pos[idx] = run;
            run += g_deg[idx];
        }
    }
    if (t == 0) g_off[N_NODES] = N_EDGES;
}

__global__ void csr_fill_kernel(const int* __restrict__ dst) {
    int e = blockIdx.x * blockDim.x + threadIdx.x;
    if (e >= N_EDGES) return;
    int p = atomicAdd(&g_pos[dst[e]], 1);
    g_eidx[p] = e;
}

// ---------------- mma.sync GEMM: C = A[M,K] @ B[N,K]^T (bf16x2 A, bf16 B) ----
// BM=128, BN=128, BK=32, 256 threads, warp tile 32x64 (2x8 m16n8k16 frags).
// C = (Ah + Al) * Bh : 2 MMAs per fragment pair (B_lo term dropped;
// error ~eps/sqrt(K) ~ 2e-4 << 1e-3 threshold).
// Smem stage (30720 B): A_h@0, A_l@10240, B_h@20480; row stride 80 B.
#define STAGE_BYTES 30720
#define GEMM_SMEM   (2 * STAGE_BYTES)

__device__ __forceinline__ void gemm_prefetch(
    uint32_t sbase, int s, int tid, int m0, int n0, int kb, int K,
    const __nv_bfloat16* Ah, const __nv_bfloat16* Al,
    const __nv_bfloat16* Bh) {
    uint32_t sp = sbase + s * STAGE_BYTES;
    int row  = tid >> 1;
    int half = tid & 1;
    uint32_t cb = (uint32_t)half * 32;
    size_t goff = (size_t)kb + (size_t)half * 16;
    uint32_t da = sp + row * 80 + cb;
    const __nv_bfloat16* pa  = Ah + (size_t)(m0 + row) * K + goff;
    const __nv_bfloat16* pal = Al + (size_t)(m0 + row) * K + goff;
    cp16(da, pa);              cp16(da + 16, pa + 8);
    cp16(da + 10240, pal);     cp16(da + 10240 + 16, pal + 8);
    uint32_t db = sp + 20480 + row * 80 + cb;
    const __nv_bfloat16* pb  = Bh + (size_t)(n0 + row) * K + goff;
    cp16(db, pb);              cp16(db + 16, pb + 8);
    asm volatile("cp.async.commit_group;" ::: "memory");
}

__global__ __launch_bounds__(256) void gemm_mma_kernel(
    const __nv_bfloat16* __restrict__ Ah, const __nv_bfloat16* __restrict__ Al,
    const __nv_bfloat16* __restrict__ Bh,
    const float* __restrict__ bias, const float* __restrict__ addend,
    float* __restrict__ outf,
    __nv_bfloat16* __restrict__ oh, __nv_bfloat16* __restrict__ ol,
    int K, int Ntot, int mode) {
    extern __shared__ char smem[];
    const uint32_t sbase = smem_u32(smem);
    const int tid = threadIdx.x;
    const int wid = tid >> 5, lane = tid & 31;
    const int wm = wid & 3, wn = wid >> 2;      // wm 0..3, wn 0..1
    const int m0 = blockIdx.y * 128;
    const int n0 = blockIdx.x * 128;

    float acc[2][8][4];
    #pragma unroll
    for (int i = 0; i < 2; i++)
        #pragma unroll
        for (int j = 0; j < 8; j++)
            #pragma unroll
            for (int q = 0; q < 4; q++) acc[i][j][q] = 0.f;

    const int nk = K >> 5;
    gemm_prefetch(sbase, 0, tid, m0, n0, 0, K, Ah, Al, Bh);

    const int r16 = lane & 15, ah8 = (lane >> 4) * 8;
    const int b8  = lane & 7;
    const int bmi = lane >> 3;
    const int bni = (bmi >> 1) * 8;
    const int bk8 = (bmi & 1) * 8;

    for (int kt = 0; kt < nk; kt++) {
        asm volatile("cp.async.wait_group 0;" ::: "memory");
        __syncthreads();
        if (kt + 1 < nk)
            gemm_prefetch(sbase, (kt + 1) & 1, tid, m0, n0, (kt + 1) << 5, K, Ah, Al, Bh);
        uint32_t sp = sbase + (kt & 1) * STAGE_BYTES;
        #pragma unroll
        for (int ks = 0; ks < 2; ks++) {
            uint32_t ahf[2][4], alf[2][4], bhf[8][2];
            #pragma unroll
            for (int mi = 0; mi < 2; mi++) {
                uint32_t a = sp + (uint32_t)(wm * 32 + mi * 16 + r16) * 80
                           + (uint32_t)(ks * 16 + ah8) * 2;
                ldsm_x4(ahf[mi], a);
                ldsm_x4(alf[mi], a + 10240);
            }
            #pragma unroll
            for (int pi = 0; pi < 4; pi++) {
                uint32_t a = sp + 20480
                           + (uint32_t)(wn * 64 + pi * 16 + bni + b8) * 80
                           + (uint32_t)(ks * 16 + bk8) * 2;
                uint32_t r[4];
                ldsm_x4(r, a);
                bhf[pi*2][0] = r[0]; bhf[pi*2][1] = r[1];
                bhf[pi*2+1][0] = r[2]; bhf[pi*2+1][1] = r[3];
            }
            #pragma unroll
            for (int mi = 0; mi < 2; mi++)
                #pragma unroll
                for (int ni = 0; ni < 8; ni++) {
                    mma16816(acc[mi][ni], ahf[mi], bhf[ni]);
                    mma16816(acc[mi][ni], alf[mi], bhf[ni]);
                }
        }
        __syncthreads();
    }

    // ---- epilogue ----
    const int rb = m0 + wm * 32 + (lane >> 2);
    const int cb = n0 + wn * 64 + (lane & 3) * 2;
    #pragma unroll
    for (int mi = 0; mi < 2; mi++) {
        #pragma unroll
        for (int half = 0; half < 2; half++) {
            int row = rb + mi * 16 + half * 8;
            if (row >= N_NODES) continue;
            #pragma unroll
            for (int ni = 0; ni < 8; ni++) {
                int col = cb + ni * 8;
                float v0 = acc[mi][ni][half * 2 + 0] + bias[col];
                float v1 = acc[mi][ni][half * 2 + 1] + bias[col + 1];
                if (mode == 0) {
                    *(float2*)(outf + (size_t)row * Ntot + col) = make_float2(v0, v1);
                } else if (mode == 2) {
                    const float* ap = addend + (size_t)row * Ntot + col;
                    *(float2*)(outf + (size_t)row * Ntot + col) =
                        make_float2(v0 + ap[0], v1 + ap[1]);
                } else {
                    v0 = 0.5f * v0 * (1.f + erff(v0 * 0.70710678118654752f));
                    v1 = 0.5f * v1 * (1.f + erff(v1 * 0.70710678118654752f));
                    __nv_bfloat16 h0 = __float2bfloat16(v0), h1 = __float2bfloat16(v1);
                    __nv_bfloat162 hh, ll;
                    hh.x = h0; hh.y = h1;
                    ll.x = __float2bfloat16(v0 - __bfloat162float(h0));
                    ll.y = __float2bfloat16(v1 - __bfloat162float(h1));
                    size_t base = (size_t)row * Ntot + col;
                    *(__nv_bfloat162*)(oh + base) = hh;
                    *(__nv_bfloat162*)(ol + base) = ll;
                }
            }
        }
    }
}

// ---------------- edge scores: warp per CSR position, 8 heads ----------------
__global__ void score_kernel(const int* __restrict__ src, const int* __restrict__ dst) {
    int pos = blockIdx.x * 8 + (threadIdx.x >> 5);
    if (pos >= N_EDGES) return;
    int e = g_eidx[pos];
    int lane = threadIdx.x & 31;
    int h = lane >> 2, sub = lane & 3;
    int s = src[e], d = dst[e];
    const float4* qp = (const float4*)(g_qkv + (size_t)s * 768 + h * DHEAD + sub * 8);
    const float4* kp = (const float4*)(g_qkv + (size_t)d * 768 + 256 + h * DHEAD + sub * 8);
    float4 q0 = qp[0], q1 = qp[1];
    float4 k0 = kp[0], k1 = kp[1];
    float p = q0.x*k0.x + q0.y*k0.y + q0.z*k0.z + q0.w*k0.w
            + q1.x*k1.x + q1.y*k1.y + q1.z*k1.z + q1.w*k1.w;
    p += __shfl_xor_sync(0xFFFFFFFFu, p, 1);
    p += __shfl_xor_sync(0xFFFFFFFFu, p, 2);
    if (sub == 0) {
        g_scores[(size_t)h * N_EDGES + pos] = p * QK_SCALE;
    }
}

// ---------------- softmax + aggregate (gather, no atomics, MLP-4 unroll) -----
__global__ __launch_bounds__(256) void aggregate_csr_kernel(
    const int* __restrict__ src, const float* __restrict__ triplet) {
    __shared__ int s_src[128];
    int node = blockIdx.x;
    int lane = threadIdx.x & 31;
    int h = threadIdx.x >> 5;
    int beg = g_off[node];
    int deg = g_off[node + 1] - beg;

    const float* sc_base = g_scores + (size_t)h * N_EDGES + beg;
    const float* vbase = g_qkv + 512 + h * 32 + lane;

    float m = -INFINITY;
    for (int i = lane; i < deg; i += 32) m = fmaxf(m, sc_base[i]);
    #pragma unroll
    for (int o = 16; o > 0; o >>= 1) m = fmaxf(m, __shfl_xor_sync(0xFFFFFFFFu, m, o));

    float acc = 0.f, ssum = 0.f;
    for (int base = 0; base < deg; base += 128) {
        int cnt = min(128, deg - base);
        __syncthreads();
        for (int i = threadIdx.x; i < cnt; i += 256)
            s_src[i] = src[g_eidx[beg + base + i]];
        __syncthreads();
        for (int c0 = 0; c0 < cnt; c0 += 32) {
            int i = c0 + lane;
            float w = (i < cnt) ? expf(sc_base[base + i] - m) : 0.f;
            ssum += w;
            int cc = min(32, cnt - c0);
            int jj = 0;
            for (; jj + 4 <= cc; jj += 4) {
                float w0 = __shfl_sync(0xFFFFFFFFu, w, jj);
                float w1 = __shfl_sync(0xFFFFFFFFu, w, jj + 1);
                float w2 = __shfl_sync(0xFFFFFFFFu, w, jj + 2);
                float w3 = __shfl_sync(0xFFFFFFFFu, w, jj + 3);
                int s0 = s_src[c0 + jj],     s1 = s_src[c0 + jj + 1];
                int s2 = s_src[c0 + jj + 2], s3 = s_src[c0 + jj + 3];
                float v0 = vbase[(size_t)s0 * 768];
                float v1 = vbase[(size_t)s1 * 768];
                float v2 = vbase[(size_t)s2 * 768];
                float v3 = vbase[(size_t)s3 * 768];
                acc += v0 * w0;
                acc += v1 * w1;
                acc += v2 * w2;
                acc += v3 * w3;
            }
            for (; jj < cc; jj++) {
                float wj = __shfl_sync(0xFFFFFFFFu, w, jj);
                int sj = s_src[c0 + jj];
                acc += vbase[(size_t)sj * 768] * wj;
            }
        }
    }
    #pragma unroll
    for (int o = 16; o > 0; o >>= 1) ssum += __shfl_xor_sync(0xFFFFFFFFu, ssum, o);
    float res = (ssum > 0.f) ? acc / ssum : 0.f;
    size_t idx = (size_t)node * DIM + h * 32 + lane;
    g_x[idx] = triplet[idx] + res;
}

// ---------------- launch ----------------
template <typename T>
static T* symaddr(const void* sym) {
    void* p = nullptr;
    cudaGetSymbolAddress(&p, sym);
    return (T*)p;
}

extern "C" void kernel_launch(void* const* d_in, const int* in_sizes, int n_in,
                              void* d_out, int out_size) {
    const float* triplet = (const float*)d_in[0];
    const int*   src     = (const int*)d_in[1];
    const int*   dst     = (const int*)d_in[2];
    const float* Wqkv    = (const float*)d_in[3];
    const float* bqkv    = (const float*)d_in[4];
    const float* lnag    = (const float*)d_in[5];
    const float* lnab    = (const float*)d_in[6];
    const float* lnrg    = (const float*)d_in[7];
    const float* lnrb    = (const float*)d_in[8];
    const float* W_in    = (const float*)d_in[9];
    const float* b_in    = (const float*)d_in[10];
    const float* W_out   = (const float*)d_in[11];
    const float* b_out   = (const float*)d_in[12];
    float* out = (float*)d_out;

    static bool init_done = false;
    static cudaStream_t s2;
    static cudaEvent_t ev_fork, ev_join;
    if (!init_done) {
        cudaFuncSetAttribute(gemm_mma_kernel, cudaFuncAttributeMaxDynamicSharedMemorySize,
                             GEMM_SMEM);
        cudaStreamCreateWithFlags(&s2, cudaStreamNonBlocking);
        cudaEventCreateWithFlags(&ev_fork, cudaEventDisableTiming);
        cudaEventCreateWithFlags(&ev_join, cudaEventDisableTiming);
        init_done = true;
    }

    float* qkv = symaddr<float>(g_qkv);
    float* x   = symaddr<float>(g_x);
    __nv_bfloat16* hln_h = symaddr<__nv_bfloat16>(g_hln_h);
    __nv_bfloat16* hln_l = symaddr<__nv_bfloat16>(g_hln_l);
    __nv_bfloat16* yln_h = symaddr<__nv_bfloat16>(g_yln_h);
    __nv_bfloat16* yln_l = symaddr<__nv_bfloat16>(g_yln_l);
    __nv_bfloat16* hid_h = symaddr<__nv_bfloat16>(g_hid_h);
    __nv_bfloat16* hid_l = symaddr<__nv_bfloat16>(g_hid_l);
    __nv_bfloat16* wq_h = symaddr<__nv_bfloat16>(g_wq_h);
    __nv_bfloat16* wi_h = symaddr<__nv_bfloat16>(g_wi_h);
    __nv_bfloat16* wo_h = symaddr<__nv_bfloat16>(g_wo_h);

    dim3 lnblk(32, 8);

    // fork side stream: CSR build + FFN weight prep (needed only later)
    cudaEventRecord(ev_fork, 0);
    cudaStreamWaitEvent(s2, ev_fork, 0);
    csr_zero_kernel<<<(N_NODES + 255) / 256, 256, 0, s2>>>();
    csr_count_kernel<<<(N_EDGES + 255) / 256, 256, 0, s2>>>(dst);
    csr_scan_kernel<<<1, 1024, 0, s2>>>();
    csr_fill_kernel<<<(N_EDGES + 255) / 256, 256, 0, s2>>>(dst);
    wprep_kernel<<<(256 * 1024 + 255) / 256, 256, 0, s2>>>(W_in, wi_h, 256, 1024);
    wprep_kernel<<<(1024 * 256 + 255) / 256, 256, 0, s2>>>(W_out, wo_h, 1024, 256);
    cudaEventRecord(ev_join, s2);

    // main stream: QKV pipeline
    wprep_kernel<<<(256 * 768 + 255) / 256, 256>>>(Wqkv, wq_h, 256, 768);
    ln_split_kernel<<<N_NODES / 8, lnblk>>>(triplet, lnag, lnab, hln_h, hln_l);
    gemm_mma_kernel<<<dim3(768 / 128, M_PAD / 128), 256, GEMM_SMEM>>>(
        hln_h, hln_l, wq_h, bqkv, nullptr, qkv, nullptr, nullptr, 256, 768, 0);

    // join: score/aggregate need CSR
    cudaStreamWaitEvent(0, ev_join, 0);
    score_kernel<<<N_EDGES / 8, 256>>>(src, dst);
    aggregate_csr_kernel<<<N_NODES, 256>>>(src, triplet);

    // LN2 + FFN
    ln_split_kernel<<<N_NODES / 8, lnblk>>>(x, lnrg, lnrb, yln_h, yln_l);
    gemm_mma_kernel<<<dim3(DFF / 128, M_PAD / 128), 256, GEMM_SMEM>>>(
        yln_h, yln_l, wi_h, b_in, nullptr, nullptr, hid_h, hid_l, 256, DFF, 1);
    gemm_mma_kernel<<<dim3(DIM / 128, M_PAD / 128), 256, GEMM_SMEM>>>(
        hid_h, hid_l, wo_h, b_out, x, out, nullptr, nullptr, DFF, DIM, 2);
}